// round 16
// baseline (speedup 1.0000x reference)
#include <cuda_runtime.h>
#include <cstdint>
#include <cstddef>

// Dims fixed: B=32, S=512, H=1024, fp32.
#define Bb   32
#define Ss   512
#define Hh   1024
#define NCTA 128
#define NTHR 256     // bi_kernel threads
#define NTS  128     // seq_kernel threads (2 outputs per thread)
#define RPAD 1028    // padded SMEM act row stride (floats): conflict-free LDS.128
#define W_F4   (3 * 8 * 256)            // 6144 float4 of weights
#define SMEM_DYN ((3 * 8 * 1024 + Bb * RPAD) * 4)   // 229,888 B

// ---- device scratch (allocation-free rule: __device__ globals) -------------
__device__ __align__(16) float4 g_WT4[256 * 1024];  // Wb [kq][c] for bi_kernel
__device__ __align__(16) float g_Bi[(size_t)Ss * Bb * Hh]; // tanh(x_t W_b^T + b_b)
__device__ __align__(16) float g_h [Bb * Hh];
__device__ __align__(16) float g_hi[Bb * Hh];
__device__ __align__(16) float g_ri[Bb * Hh];
__device__ __align__(128) unsigned g_arrive;
__device__ __align__(128) unsigned g_release;

__global__ void init_kernel() {
    int i = blockIdx.x * blockDim.x + threadIdx.x;
    if (i < Bb * Hh) g_h[i] = 0.0f;
    if (i == 0) { g_arrive = 0u; g_release = 0u; }
}

// ---------------------------------------------------------------------------
// XLA EmitFastTanh, FMA variant (verified bit-exact R8-R14).
__device__ __forceinline__ float xla_tanh(float x) {
    float z = fminf(x, 7.99881172180175781f);
    z = fmaxf(z, -7.99881172180175781f);
    float x2 = __fmul_rn(z, z);
    float p = __fmaf_rn(x2, -2.76076847742355e-16f, 2.00018790482477e-13f);
    p = __fmaf_rn(x2, p, -8.60467152213735e-11f);
    p = __fmaf_rn(x2, p,  5.12229709037114e-08f);
    p = __fmaf_rn(x2, p,  1.48572235717979e-05f);
    p = __fmaf_rn(x2, p,  6.37261928875436e-04f);
    p = __fmaf_rn(x2, p,  4.89352455891786e-03f);
    p = __fmul_rn(z, p);
    float q = __fmaf_rn(x2, 1.19825839466702e-06f, 1.18534705686654e-04f);
    q = __fmaf_rn(x2, q, 2.26843463243900e-03f);
    q = __fmaf_rn(x2, q, 4.89352518554385e-03f);
    return (fabsf(x) < 0.0004f) ? x : __fdiv_rn(p, q);
}

// ---------------------------------------------------------------------------
// Wb transpose into [kq][c] layout for bi_kernel. Pure copy (bit-free).
__global__ void transpose_kernel(const float* __restrict__ Wb) {
    int i = blockIdx.x * blockDim.x + threadIdx.x;   // 0 .. 262143
    if (i >= 262144) return;
    int kq = i >> 10;
    int c  = i & 1023;
    g_WT4[i] = ((const float4*)Wb)[(size_t)c * 256 + kq];
}

// ---------------------------------------------------------------------------
// Bi precompute (verified bit order R8-R14; fp32-FMA-roofline-bound ~0.95 ms).
__global__ __launch_bounds__(NTHR, 1) void bi_kernel(
    const float* __restrict__ x, const float* __restrict__ bbias)
{
    __shared__ float xs[Bb][128];
    const int tid = threadIdx.x;
    const int t   = blockIdx.y;
    const int c   = blockIdx.x * NTHR + tid;
    const float4* wt = g_WT4 + c;                // stride 1024 float4 per kq

    float acc[Bb];
    #pragma unroll
    for (int b = 0; b < Bb; b++) acc[b] = 0.0f;

    for (int kp = 0; kp < 8; kp++) {             // 8 panels of 128 k
        __syncthreads();
        #pragma unroll
        for (int j = 0; j < 4; j++) {
            int i  = tid + j * NTHR;             // 0..1023 float4s
            int b  = i >> 5;
            int kl = i & 31;
            ((float4*)&xs[b][0])[kl] =
                *(const float4*)(x + ((size_t)b * Ss + t) * Hh + kp * 128 + kl * 4);
        }
        __syncthreads();
        #pragma unroll 1
        for (int kl = 0; kl < 32; kl++) {
            float4 w = wt[(kp * 32 + kl) * 1024];
            #pragma unroll
            for (int b = 0; b < Bb; b++) {
                float4 a = *(const float4*)&xs[b][kl * 4];
                acc[b] = __fmaf_rn(a.x, w.x, acc[b]);
                acc[b] = __fmaf_rn(a.y, w.y, acc[b]);
                acc[b] = __fmaf_rn(a.z, w.z, acc[b]);
                acc[b] = __fmaf_rn(a.w, w.w, acc[b]);
            }
        }
    }

    float bias = bbias[c];
    #pragma unroll
    for (int b = 0; b < Bb; b++)
        g_Bi[((size_t)t * Bb + b) * Hh + c] = xla_tanh(__fadd_rn(acc[b], bias));
}

// ---------------------------------------------------------------------------
// Grid barrier: single-counter contention-split form, verified in four
// consecutive passing rounds (R10, R13, R14 + R9 variant).
__device__ __forceinline__ void gsync(unsigned* epoch) {
    unsigned e = ++(*epoch);
    __syncthreads();
    if (threadIdx.x == 0) {
        __threadfence();
        unsigned a = atomicAdd(&g_arrive, 1u);
        if (a == e * NCTA - 1u) {
            asm volatile("st.release.gpu.u32 [%0], %1;"
                         :: "l"(&g_release), "r"(e));
        }
        unsigned v;
        do {
            asm volatile("ld.acquire.gpu.u32 %0, [%1];" : "=r"(v) : "l"(&g_release));
        } while (v < e);
    }
    __syncthreads();
}

// ---------------------------------------------------------------------------
// Dual-output dot over one 64-kq chunk: TWO independent single-accumulator
// ascending-k chains, accumulators carried across chunks by the caller =>
// each output's chain is bit-identical to the frozen R8 order.
__device__ __forceinline__ void dot2_chunk(const float4* __restrict__ wpA,
                                           const float4* __restrict__ wpB,
                                           const float4* __restrict__ ap,
                                           int k0, float& a0, float& a1) {
    #pragma unroll 8
    for (int kq = k0; kq < k0 + 64; kq++) {
        float4 wA = wpA[kq * 8];
        float4 wB = wpB[kq * 8];
        float4 a  = ap[kq];
        a0 = __fmaf_rn(a.x, wA.x, a0);  a1 = __fmaf_rn(a.x, wB.x, a1);
        a0 = __fmaf_rn(a.y, wA.y, a0);  a1 = __fmaf_rn(a.y, wB.y, a1);
        a0 = __fmaf_rn(a.z, wA.z, a0);  a1 = __fmaf_rn(a.z, wB.z, a1);
        a0 = __fmaf_rn(a.w, wA.w, a0);  a1 = __fmaf_rn(a.w, wB.w, a1);
    }
}

// Stage one 64-kq chunk of all 32 rows (2048 float4; 16 per thread).
// Consecutive lanes -> consecutive kq within a row: LDG.128 coalesced.
__device__ __forceinline__ void stage_chunk(float* __restrict__ s,
                                            const float* __restrict__ src,
                                            int k0) {
    int tid = threadIdx.x;
    #pragma unroll
    for (int j = 0; j < 16; j++) {
        int i   = tid + j * NTS;        // 0..2047 ; i = r*64 + kql
        int r   = i >> 6;
        int kq  = k0 + (i & 63);
        *(float4*)(s + r * RPAD + kq * 4) = ((const float4*)src)[r * 256 + kq];
    }
}

// Stage fl(ri + pe) for one chunk: single rounded add per element (the
// reference's literal elementwise (ri + p_t)); chain order untouched.
__device__ __forceinline__ void stage_add_chunk(float* __restrict__ s,
                                                const float* __restrict__ r0,
                                                const float* __restrict__ pe,
                                                int t, int k0) {
    int tid = threadIdx.x;
    #pragma unroll
    for (int j = 0; j < 16; j++) {
        int i   = tid + j * NTS;
        int r   = i >> 6;
        int kq  = k0 + (i & 63);
        float4 a = ((const float4*)r0)[r * 256 + kq];
        float4 q = *(const float4*)(pe + ((size_t)r * Ss + t) * Hh + kq * 4);
        float4 v;
        v.x = __fadd_rn(a.x, q.x); v.y = __fadd_rn(a.y, q.y);
        v.z = __fadd_rn(a.z, q.z); v.w = __fadd_rn(a.w, q.w);
        *(float4*)(s + r * RPAD + kq * 4) = v;
    }
}

// ---------------------------------------------------------------------------
// Sequential recurrence, weight-stationary, chunk-pipelined. CTA cb owns cols
// [cb*8, cb*8+8) x all 32 rows; 128 threads x 2 outputs (c0+u, c0+u+4).
// Per phase: stage chunk0; then for each chunk: issue stage of chunk+1,
// dot chunk, syncthreads — staging hides under compute.
__global__ __launch_bounds__(NTS, 1) void seq_kernel(
    const float* __restrict__ pe,
    const float* __restrict__ Whb, const float* __restrict__ Wr,
    const float* __restrict__ Wb,
    const float* __restrict__ bb,  const float* __restrict__ bhb,
    const float* __restrict__ br,
    float* __restrict__ out)
{
    extern __shared__ float smem[];
    float4* w_s4  = (float4*)smem;            // [3][256][8] float4 = 96KB
    float*  s_act = smem + 3 * 8 * 1024;      // [32][RPAD]

    const int tid  = threadIdx.x;
    const int lane = tid & 31;
    const int w    = tid >> 5;
    const int c0   = blockIdx.x * 8;
    const int u    = lane >> 3;               // 0..3 (col pair)
    const int bl   = lane & 7;                // 0..7
    const int rl   = w * 8 + bl;              // batch row 0..31
    const int cA   = c0 + u;
    const int cB   = c0 + u + 4;
    const int oA   = rl * Hh + cA;
    const int oB   = rl * Hh + cB;

    // prologue: load this CTA's 8 columns of all three weight matrices.
    for (int idx = tid; idx < W_F4; idx += NTS) {
        int m   = idx >> 11;
        int kq  = (idx >> 3) & 255;
        int cl2 = idx & 7;
        const float* Wm = (m == 0) ? Whb : (m == 1) ? Wr : Wb;
        w_s4[idx] = ((const float4*)Wm)[(size_t)(c0 + cl2) * 256 + kq];
    }
    __syncthreads();

    const float4* wpA_hb = w_s4 + 0 * 2048 + u;
    const float4* wpA_r  = w_s4 + 1 * 2048 + u;
    const float4* wpA_b  = w_s4 + 2 * 2048 + u;
    const float4* ap     = (const float4*)(s_act + rl * RPAD);

    const float bias_hbA = bhb[cA], bias_hbB = bhb[cB];
    const float bias_rA  = br[cA],  bias_rB  = br[cB];
    const float bias_bA  = bb[cA],  bias_bB  = bb[cB];

    unsigned epoch = 0u;
    float hiA = 0.0f, hiB = 0.0f;

    #pragma unroll 1
    for (int t = 0; t < Ss; t++) {
        float zA, zB;

        // sub 1: hi = tanh(h @ W_hb^T + b_hb) + bi[t]
        stage_chunk(s_act, g_h, 0);
        float biA = g_Bi[((size_t)t * Bb + rl) * Hh + cA];
        float biB = g_Bi[((size_t)t * Bb + rl) * Hh + cB];
        __syncthreads();
        zA = 0.0f; zB = 0.0f;
        #pragma unroll
        for (int ck = 0; ck < 4; ck++) {
            if (ck < 3) stage_chunk(s_act, g_h, (ck + 1) * 64);
            dot2_chunk(wpA_hb, wpA_hb + 4, ap, ck * 64, zA, zB);
            __syncthreads();
        }
        hiA = __fadd_rn(xla_tanh(__fadd_rn(zA, bias_hbA)), biA);
        hiB = __fadd_rn(xla_tanh(__fadd_rn(zB, bias_hbB)), biB);
        g_hi[oA] = hiA; g_hi[oB] = hiB;
        gsync(&epoch);

        // sub 2: ri = tanh(hi @ W_r^T + b_r)
        stage_chunk(s_act, g_hi, 0);
        __syncthreads();
        zA = 0.0f; zB = 0.0f;
        #pragma unroll
        for (int ck = 0; ck < 4; ck++) {
            if (ck < 3) stage_chunk(s_act, g_hi, (ck + 1) * 64);
            dot2_chunk(wpA_r, wpA_r + 4, ap, ck * 64, zA, zB);
            __syncthreads();
        }
        g_ri[oA] = xla_tanh(__fadd_rn(zA, bias_rA));
        g_ri[oB] = xla_tanh(__fadd_rn(zB, bias_rB));
        gsync(&epoch);

        // sub 3: h = hi + tanh((ri + p_t) @ W_b^T + b_b)
        stage_add_chunk(s_act, g_ri, pe, t, 0);
        __syncthreads();
        zA = 0.0f; zB = 0.0f;
        #pragma unroll
        for (int ck = 0; ck < 4; ck++) {
            if (ck < 3) stage_add_chunk(s_act, g_ri, pe, t, (ck + 1) * 64);
            dot2_chunk(wpA_b, wpA_b + 4, ap, ck * 64, zA, zB);
            __syncthreads();
        }
        float hnA = __fadd_rn(hiA, xla_tanh(__fadd_rn(zA, bias_bA)));
        float hnB = __fadd_rn(hiB, xla_tanh(__fadd_rn(zB, bias_bB)));
        g_h[oA] = hnA; g_h[oB] = hnB;
        if (t == Ss - 1) { out[oA] = hnA; out[oB] = hnB; }
        gsync(&epoch);
    }
}

// ---------------------------------------------------------------------------
extern "C" void kernel_launch(void* const* d_in, const int* in_sizes, int n_in,
                              void* d_out, int out_size) {
    const float* x   = (const float*)d_in[0];
    const float* pe  = (const float*)d_in[1];
    const float* Wb  = (const float*)d_in[2];
    const float* bb  = (const float*)d_in[3];
    const float* Whb = (const float*)d_in[4];
    const float* bhb = (const float*)d_in[5];
    const float* Wr  = (const float*)d_in[6];
    const float* br  = (const float*)d_in[7];
    float* out = (float*)d_out;

    cudaFuncSetAttribute(seq_kernel, cudaFuncAttributeMaxDynamicSharedMemorySize,
                         SMEM_DYN);

    init_kernel<<<(Bb * Hh + 255) / 256, 256>>>();
    transpose_kernel<<<(262144 + 255) / 256, 256>>>(Wb);
    bi_kernel<<<dim3(Hh / NTHR, Ss), NTHR>>>(x, bb);
    seq_kernel<<<NCTA, NTS, SMEM_DYN>>>(pe, Whb, Wr, Wb, bb, bhb, br, out);
}